// round 12
// baseline (speedup 1.0000x reference)
#include <cuda_runtime.h>
#include <cuda_bf16.h>
#include <cstdint>

#define N_USER 100000
#define N_ITEM 50000
#define N_NODES 150000
#define N_EDGES 1200000
#define D 64
#define OUTD 256
#define NEG_SLOPE 0.01f
#define EPS_NORM 1e-12f

// Scratch (device globals; no dynamic allocation)
__device__ float g_EA[N_NODES * D];       // E ping
__device__ float g_EB[N_NODES * D];       // E pong
__device__ float4 g_Wpack[3 * 2048];      // packed W quads per layer
__device__ int g_cnt[N_NODES];            // degree histogram (re-zeroed each replay)
__device__ int g_off[N_NODES];            // row range start
__device__ int g_end[N_NODES];            // row range end
__device__ int g_cur[N_NODES];            // scatter cursors
__device__ float2 g_edge[N_EDGES];        // {bitcast(col), val}
__device__ int g_total;                   // global edge-slot cursor

// ---------------------------------------------------------------------------
// helpers
// ---------------------------------------------------------------------------
__device__ __forceinline__ float lrelu(float v) {
    return v >= 0.f ? v : NEG_SLOPE * v;
}
__device__ __forceinline__ unsigned long long pk2(float lo, float hi) {
    unsigned long long r;
    asm("mov.b64 %0, {%1, %2};" : "=l"(r) : "f"(lo), "f"(hi));
    return r;
}
__device__ __forceinline__ void unpk2(float& lo, float& hi, unsigned long long v) {
    asm("mov.b64 {%0, %1}, %2;" : "=f"(lo), "=f"(hi) : "l"(v));
}
__device__ __forceinline__ void fma2(unsigned long long& d, unsigned long long a,
                                     unsigned long long b) {
    asm("fma.rn.f32x2 %0, %1, %2, %0;" : "+l"(d) : "l"(a), "l"(b));
}

// ---------------------------------------------------------------------------
// CSR build: hist -> offsets (warp scan + global atomic) -> scatter
// Row ranges are disjoint but not globally ordered (order irrelevant).
// ---------------------------------------------------------------------------
__global__ void k_hist(const int* __restrict__ erow) {
    int e = blockIdx.x * blockDim.x + threadIdx.x;
    if (e >= N_EDGES) return;
    atomicAdd(&g_cnt[__ldg(&erow[e])], 1);
}

__global__ void k_offsets() {
    int i = blockIdx.x * blockDim.x + threadIdx.x;
    int lane = threadIdx.x & 31;
    int v = (i < N_NODES) ? g_cnt[i] : 0;
    int s = v;                                   // inclusive warp scan
    #pragma unroll
    for (int d = 1; d < 32; d <<= 1) {
        int t = __shfl_up_sync(0xffffffffu, s, d);
        if (lane >= d) s += t;
    }
    int wtotal = __shfl_sync(0xffffffffu, s, 31);
    int base = 0;
    if (lane == 0 && wtotal > 0) base = atomicAdd(&g_total, wtotal);
    base = __shfl_sync(0xffffffffu, base, 0);
    if (i < N_NODES) {
        int start = base + s - v;
        g_off[i] = start;
        g_cur[i] = start;
        g_end[i] = start + v;
        g_cnt[i] = 0;                            // reset for next replay
    }
}

__global__ void k_scatter(const int* __restrict__ erow, const int* __restrict__ ecol,
                          const float* __restrict__ eval_) {
    int e = blockIdx.x * blockDim.x + threadIdx.x;
    if (e == 0) g_total = 0;                     // reset cursor for next replay
    if (e >= N_EDGES) return;
    int r = __ldg(&erow[e]);
    int pos = atomicAdd(&g_cur[r], 1);
    g_edge[pos] = make_float2(__int_as_float(__ldg(&ecol[e])), __ldg(&eval_[e]));
}

// ---------------------------------------------------------------------------
// kernel P: pack W for all 3 layers
// g_Wpack[l*2048 + k*32 + j] = { Wf[j][k], Wf[j+32][k], Wb[j][k], Wb[j+32][k] }
// ---------------------------------------------------------------------------
__global__ void k_prep(const float* __restrict__ Wf, const float* __restrict__ Wb) {
    int u = blockIdx.x * blockDim.x + threadIdx.x;
    if (u >= 3 * 2048) return;
    int l = u >> 11;
    int t = u & 2047;
    int k = t >> 5;
    int j = t & 31;
    const float* wf = Wf + l * D * D;
    const float* wb = Wb + l * D * D;
    g_Wpack[u] = make_float4(wf[j * D + k], wf[(j + 32) * D + k],
                             wb[j * D + k], wb[(j + 32) * D + k]);
}

// ---------------------------------------------------------------------------
// kernel 0: build E0 = concat(user, item) into g_EA; write out[:, 0:64]
// ---------------------------------------------------------------------------
__global__ void k_init(const float* __restrict__ user, const float* __restrict__ item,
                       float* __restrict__ out) {
    int idx = blockIdx.x * blockDim.x + threadIdx.x;
    if (idx >= N_NODES * (D / 4)) return;
    int row = idx >> 4;
    int c4 = (idx & 15) << 2;
    float4 v;
    if (row < N_USER)
        v = *reinterpret_cast<const float4*>(&user[row * D + c4]);
    else
        v = *reinterpret_cast<const float4*>(&item[(row - N_USER) * D + c4]);
    *reinterpret_cast<float4*>(&g_EA[row * D + c4]) = v;
    *reinterpret_cast<float4*>(&out[row * OUTD + c4]) = v;
}

// ---------------------------------------------------------------------------
// fused layer kernel: spmm (CSR gather, registers) + dense + norm.
//   front[r] = Ein[r] + sum val*Ein[col]   (in registers)
//   o = lrelu(front @ Wf^T + bf) + lrelu((Ein*front) @ Wb^T + bb)
//   Eout <- o (if keepE) ; out[:, 64*(l+1):...] = o/||o||
// blockDim (32,8). Warp = 8 rows as 4 f32x2 row pairs.
// W copy + __syncthreads happen BEFORE gather: after that point warps flow
// gather -> dense -> epilogue independently (cross-warp phase mixing).
// ---------------------------------------------------------------------------
#define GROUPS (N_NODES / 8)          // 18750
#define LAYER_WARPS 8
#define LAYER_BLOCKS ((GROUPS + LAYER_WARPS - 1) / LAYER_WARPS)

__global__ __launch_bounds__(32 * LAYER_WARPS) void k_layer(
        const float* __restrict__ bf, const float* __restrict__ bb,
        float* __restrict__ out, int layer, int flip, int keepE) {
    __shared__ float4 Wc[D * 32];                    // 32 KB, packed quads
    __shared__ float4 xy[LAYER_WARPS][4][D];         // 32 KB

    const float* Ein = flip ? g_EB : g_EA;
    float* Eout = flip ? g_EA : g_EB;

    int tid = threadIdx.y * 32 + threadIdx.x;
    int lane = threadIdx.x;
    int ty = threadIdx.y;

    // coalesced copy of pre-packed W; sync BEFORE gather so warps are
    // independent afterwards
    const float4* wsrc = g_Wpack + layer * 2048;
    #pragma unroll
    for (int t = tid; t < 2048; t += 32 * LAYER_WARPS) Wc[t] = wsrc[t];
    __syncthreads();

    int group = blockIdx.x * LAYER_WARPS + ty;
    const float2* E2 = reinterpret_cast<const float2*>(Ein);
    if (group >= GROUPS) return;
    int rb = group * 8;

    // phase 1: gather front for 4 row pairs, stage xy (per-warp smem)
    #pragma unroll
    for (int p = 0; p < 4; p++) {
        int r0 = rb + 2 * p;
        int r1 = r0 + 1;
        int i0 = __ldg(&g_off[r0]);
        int n0 = __ldg(&g_end[r0]);
        int i1 = __ldg(&g_off[r1]);
        int n1 = __ldg(&g_end[r1]);
        float2 e0v = E2[r0 * 32 + lane];
        float2 e1v = E2[r1 * 32 + lane];
        float2 acc0 = e0v;                        // +I term
        float2 acc1 = e1v;
        int m = min(n0 - i0, n1 - i1);
        for (int t = 0; t < m; t++) {
            float2 p0 = g_edge[i0 + t];
            float2 p1 = g_edge[i1 + t];
            int c0 = __float_as_int(p0.x);
            int c1 = __float_as_int(p1.x);
            float2 x0 = E2[c0 * 32 + lane];
            float2 x1 = E2[c1 * 32 + lane];
            acc0.x = fmaf(p0.y, x0.x, acc0.x);
            acc0.y = fmaf(p0.y, x0.y, acc0.y);
            acc1.x = fmaf(p1.y, x1.x, acc1.x);
            acc1.y = fmaf(p1.y, x1.y, acc1.y);
        }
        for (i0 += m; i0 < n0; i0++) {
            float2 p0 = g_edge[i0];
            int c0 = __float_as_int(p0.x);
            float2 x0 = E2[c0 * 32 + lane];
            acc0.x = fmaf(p0.y, x0.x, acc0.x);
            acc0.y = fmaf(p0.y, x0.y, acc0.y);
        }
        for (i1 += m; i1 < n1; i1++) {
            float2 p1 = g_edge[i1];
            int c1 = __float_as_int(p1.x);
            float2 x1 = E2[c1 * 32 + lane];
            acc1.x = fmaf(p1.y, x1.x, acc1.x);
            acc1.y = fmaf(p1.y, x1.y, acc1.y);
        }
        xy[ty][p][2 * lane] =
            make_float4(acc0.x, acc1.x, acc0.x * e0v.x, acc1.x * e1v.x);
        xy[ty][p][2 * lane + 1] =
            make_float4(acc0.y, acc1.y, acc0.y * e0v.y, acc1.y * e1v.y);
    }
    __syncwarp();

    // phase 2: dense
    float bfv0 = bf[lane], bfv1 = bf[lane + 32];
    float bbv0 = bb[lane], bbv1 = bb[lane + 32];

    unsigned long long sf0[4], sf1[4], sb0[4], sb1[4];
    #pragma unroll
    for (int p = 0; p < 4; p++) {
        sf0[p] = pk2(bfv0, bfv0);
        sf1[p] = pk2(bfv1, bfv1);
        sb0[p] = pk2(bbv0, bbv0);
        sb1[p] = pk2(bbv1, bbv1);
    }

    #pragma unroll 4
    for (int k = 0; k < D; k++) {
        float4 w = Wc[k * 32 + lane];
        unsigned long long wf0p = pk2(w.x, w.x);
        unsigned long long wf1p = pk2(w.y, w.y);
        unsigned long long wb0p = pk2(w.z, w.z);
        unsigned long long wb1p = pk2(w.w, w.w);
        #pragma unroll
        for (int p = 0; p < 4; p++) {
            ulonglong2 v = *reinterpret_cast<const ulonglong2*>(&xy[ty][p][k]);
            fma2(sf0[p], v.x, wf0p);
            fma2(sf1[p], v.x, wf1p);
            fma2(sb0[p], v.y, wb0p);
            fma2(sb1[p], v.y, wb1p);
        }
    }

    // phase 3: epilogue
    int ocol = (layer + 1) * D;
    #pragma unroll
    for (int p = 0; p < 4; p++) {
        float f0lo, f0hi, f1lo, f1hi, b0lo, b0hi, b1lo, b1hi;
        unpk2(f0lo, f0hi, sf0[p]);
        unpk2(f1lo, f1hi, sf1[p]);
        unpk2(b0lo, b0hi, sb0[p]);
        unpk2(b1lo, b1hi, sb1[p]);

        int row0 = rb + 2 * p;
        int row1 = row0 + 1;

        float o00 = lrelu(f0lo) + lrelu(b0lo);
        float o01 = lrelu(f1lo) + lrelu(b1lo);
        float o10 = lrelu(f0hi) + lrelu(b0hi);
        float o11 = lrelu(f1hi) + lrelu(b1hi);

        float ss0 = o00 * o00 + o01 * o01;
        float ss1 = o10 * o10 + o11 * o11;
        #pragma unroll
        for (int d = 16; d > 0; d >>= 1) {
            ss0 += __shfl_xor_sync(0xffffffffu, ss0, d);
            ss1 += __shfl_xor_sync(0xffffffffu, ss1, d);
        }
        float inv0 = 1.f / fmaxf(sqrtf(ss0), EPS_NORM);
        float inv1 = 1.f / fmaxf(sqrtf(ss1), EPS_NORM);

        if (keepE) {
            Eout[row0 * D + lane] = o00;
            Eout[row0 * D + 32 + lane] = o01;
            Eout[row1 * D + lane] = o10;
            Eout[row1 * D + 32 + lane] = o11;
        }

        out[row0 * OUTD + ocol + lane] = o00 * inv0;
        out[row0 * OUTD + ocol + 32 + lane] = o01 * inv0;
        out[row1 * OUTD + ocol + lane] = o10 * inv1;
        out[row1 * OUTD + ocol + 32 + lane] = o11 * inv1;
    }
}

// ---------------------------------------------------------------------------
extern "C" void kernel_launch(void* const* d_in, const int* in_sizes, int n_in,
                              void* d_out, int out_size) {
    const float* user = (const float*)d_in[0];
    const float* item = (const float*)d_in[1];
    const int* erow = (const int*)d_in[2];
    const int* ecol = (const int*)d_in[3];
    const float* eval_ = (const float*)d_in[4];
    const float* Wf = (const float*)d_in[5];
    const float* bf = (const float*)d_in[6];
    const float* Wb = (const float*)d_in[7];
    const float* bb = (const float*)d_in[8];
    float* out = (float*)d_out;

    const int vec_elems = N_NODES * (D / 4);
    const int vec_blocks = (vec_elems + 255) / 256;
    const int edge_blocks = (N_EDGES + 255) / 256;
    const int node_blocks = (N_NODES + 255) / 256;

    // CSR build: 3 kernels (hist, warp-scan offsets, scatter)
    k_hist<<<edge_blocks, 256>>>(erow);          // launch 0
    k_offsets<<<node_blocks, 256>>>();           // launch 1
    k_scatter<<<edge_blocks, 256>>>(erow, ecol, eval_);  // launch 2

    k_prep<<<24, 256>>>(Wf, Wb);                 // launch 3
    k_init<<<vec_blocks, 256>>>(user, item, out); // launch 4
    for (int l = 0; l < 3; l++) {                // launches 5..7
        k_layer<<<LAYER_BLOCKS, dim3(32, LAYER_WARPS)>>>(
            bf + l * D, bb + l * D, out, l, l & 1, l != 2 ? 1 : 0);
    }
}